// round 6
// baseline (speedup 1.0000x reference)
#include <cuda_runtime.h>
#include <cuda_fp16.h>
#include <math.h>

#define BATCH 8
#define CH 64
#define PLANE 50176            /* 224*224 */
#define NPLANES 512
#define HWTILES 1568           /* PLANE/32 */
#define NTILES (BATCH*HWTILES) /* 12544 */
#define POOLED_ELEMS 4194304
#define NB_INNER 512
#define NB_FILL 4096

// ---------------- device scratch ----------------
__device__ __half g_xTh[(size_t)BATCH*PLANE*CH]; // x transposed [B][H][W][C] fp16
__device__ float  g_branch[NPLANES];             // accumulated channel sums (atomic)
__device__ float  g_lohi[16];
__device__ float  g_cval[NPLANES];
__device__ float2 g_polar[8192];                 // (logr, a/pi-1)
__device__ int    g_ctr = 0;

// ---- K1: transpose->fp16 channel-packed + sums + fan-in MLP ------------
__global__ void __launch_bounds__(256) k_prep(
        const float* __restrict__ x,
        const float* __restrict__ l,
        const float* __restrict__ w1, const float* __restrict__ b1,
        const float* __restrict__ w2, const float* __restrict__ b2,
        float* __restrict__ outw) {
    __shared__ float tile[CH][33];
    __shared__ int isLast;
    int bx   = blockIdx.x;
    int b    = bx / HWTILES;
    int tidx = bx % HWTILES;
    int t0   = tidx * 32;
    int tid  = threadIdx.x;

    // load 64ch x 32px tile (coalesced float4)
    const float4* xp = (const float4*)(x + (size_t)b * CH * PLANE);
    int base4 = t0 >> 2;
#pragma unroll
    for (int it = 0; it < 2; it++) {
        int p    = it * 256 + tid;
        int c    = p >> 3;
        int col4 = p & 7;
        float4 v = xp[(size_t)c * (PLANE / 4) + base4 + col4];
        tile[c][col4 * 4 + 0] = v.x;
        tile[c][col4 * 4 + 1] = v.y;
        tile[c][col4 * 4 + 2] = v.z;
        tile[c][col4 * 4 + 3] = v.w;
    }
    __syncthreads();

    // channel sums -> atomic accumulate
    if (tid < CH) {
        float s = 0.f;
#pragma unroll
        for (int k = 0; k < 32; k++) s += tile[tid][k];
        atomicAdd(&g_branch[b * CH + tid], s);
    }

    // fp16 channel-packed store: 8 ch per uint4, 8 quads per pixel
    {
        int rr = tid >> 3;
        int q  = tid & 7;
        half2 h0 = __floats2half2_rn(tile[8*q+0][rr], tile[8*q+1][rr]);
        half2 h1 = __floats2half2_rn(tile[8*q+2][rr], tile[8*q+3][rr]);
        half2 h2 = __floats2half2_rn(tile[8*q+4][rr], tile[8*q+5][rr]);
        half2 h3 = __floats2half2_rn(tile[8*q+6][rr], tile[8*q+7][rr]);
        uint4 u;
        u.x = *(unsigned int*)&h0;
        u.y = *(unsigned int*)&h1;
        u.z = *(unsigned int*)&h2;
        u.w = *(unsigned int*)&h3;
        ((uint4*)g_xTh)[((size_t)b * PLANE + t0 + rr) * 8 + q] = u;
    }

    // block 0: polar table (data-independent)
    if (bx == 0) {
        for (int e = tid; e < 8192; e += 256) {
            int i = e >> 7, j = e & 127;
            float xg = (i - 32) * (1.0f / 32.0f);
            float yg = (j - 64) * (1.0f / 64.0f);
            float logr = logf(fmaxf(sqrtf(xg * xg + yg * yg), 1e-12f));
            float a = atan2f(yg, xg);
            if (!(a > 0.f)) a += 6.283185307179586f;
            g_polar[e] = make_float2(logr, a * 0.3183098861837907f - 1.f);
        }
    }

    // fan-in: last block runs the MLP + cval + resets
    __threadfence();
    __syncthreads();
    if (tid == 0) {
        int old = atomicAdd(&g_ctr, 1);
        isLast = (old == (int)gridDim.x - 1);
    }
    __syncthreads();
    if (!isLast) return;
    __threadfence();

    __shared__ float br[NPLANES];
    __shared__ float hid[BATCH][32];
    __shared__ float wgt[16];
    br[tid]       = g_branch[tid]       * (1.0f / (float)PLANE);
    br[tid + 256] = g_branch[tid + 256] * (1.0f / (float)PLANE);
    g_branch[tid] = 0.f;                 // reset for graph replay
    g_branch[tid + 256] = 0.f;
    __syncthreads();

    {
        int bb = tid >> 5, m = tid & 31;
        float acc = b1[m];
#pragma unroll
        for (int c = 0; c < 64; c++) acc += br[bb * 64 + c] * w1[c * 32 + m];
        hid[bb][m] = fmaxf(acc, 0.f);
    }
    __syncthreads();
    if (tid < 16) {
        int bb = tid >> 1, k = tid & 1;
        float acc = b2[k];
#pragma unroll
        for (int m = 0; m < 32; m++) acc += hid[bb][m] * w2[m * 2 + k];
        float wv = 1.f / (1.f + expf(-acc));
        wgt[tid] = wv;
        outw[tid] = wv;
    }
    __syncthreads();
    if (tid < 8) {
        g_lohi[2 * tid + 0] = logf(wgt[2 * tid + 0] * 0.01f);
        g_lohi[2 * tid + 1] = logf(wgt[2 * tid + 1] * 0.60f);
    }

    // constant-region bilinear values
#pragma unroll
    for (int rep = 0; rep < 2; rep++) {
        int idx = rep * 256 + tid;
        int bb = idx >> 6;
        float gx = l[2 * bb], gy = l[2 * bb + 1];
        float ix = fminf(fmaxf((gx + 1.f) * 112.f - 0.5f, 0.f), 223.f);
        float iy = fminf(fmaxf((gy + 1.f) * 112.f - 0.5f, 0.f), 223.f);
        float x0f = floorf(ix), y0f = floorf(iy);
        float wx = ix - x0f, wy = iy - y0f;
        int x0 = (int)x0f, y0 = (int)y0f;
        int x1 = min(x0 + 1, 223), y1 = min(y0 + 1, 223);
        const float* pp = x + (size_t)idx * PLANE;
        g_cval[idx] = pp[y0 * 224 + x0] * (1.f - wx) * (1.f - wy)
                    + pp[y0 * 224 + x1] * wx * (1.f - wy)
                    + pp[y1 * 224 + x0] * (1.f - wx) * wy
                    + pp[y1 * 224 + x1] * wx * wy;
    }
    if (tid == 0) g_ctr = 0;
}

// ---- K2: fused fill + channel-packed gather + 4x4 pool -----------------
__global__ void __launch_bounds__(256) k_fused(const float* __restrict__ l,
                                               float* __restrict__ out) {
    if (blockIdx.x >= NB_INNER) {
        int idx = (blockIdx.x - NB_INNER) * 256 + threadIdx.x;  // float4 index
        int plane = idx >> 11;
        int rem = idx & 2047;
        int h = rem >> 5, w4 = rem & 31;
        if (h < 16 && w4 < 8) return;
        float v = g_cval[plane];
        __stcs(&((float4*)out)[idx], make_float4(v, v, v, v));
        return;
    }

    __shared__ float st[8][68];
    int warpId = threadIdx.x >> 5;
    int lane   = threadIdx.x & 31;
    int wpos   = blockIdx.x * 8 + warpId;
    int b   = wpos >> 9;
    int pos = wpos & 511;
    int h = pos >> 5, w = pos & 31;
    int tap = lane >> 3, c8 = lane & 7;

    float l0 = l[2*b], l1 = l[2*b + 1];
    float lo = g_lohi[2*b], hi = g_lohi[2*b + 1];
    float inv2 = 2.f / (hi - lo);

    // lanes 0..15 compute the 16 sample coordinates
    int s16 = lane & 15;
    int i = 4 * h + (s16 >> 2);
    int j = 4 * w + (s16 & 3);
    float2 pb = g_polar[(i << 7) | j];
    float gx = pb.y + l0;
    float gy = (pb.x - lo) * inv2 - 1.f + l1;
    float ix = fminf(fmaxf((gx + 1.f) * 112.f - 0.5f, 0.f), 223.f);
    float iy = fminf(fmaxf((gy + 1.f) * 112.f - 0.5f, 0.f), 223.f);

    const uint4* xt = (const uint4*)g_xTh;
    size_t bbase = (size_t)b * PLANE * 8;
    float acc[8];
#pragma unroll
    for (int k = 0; k < 8; k++) acc[k] = 0.f;

#pragma unroll
    for (int s = 0; s < 16; s++) {
        float ixs = __shfl_sync(0xffffffffu, ix, s);
        float iys = __shfl_sync(0xffffffffu, iy, s);
        float x0f = floorf(ixs), y0f = floorf(iys);
        float wx = ixs - x0f, wy = iys - y0f;
        int x0 = (int)x0f, y0 = (int)y0f;
        int x1 = min(x0 + 1, 223), y1 = min(y0 + 1, 223);
        int xs = (tap & 1) ? x1 : x0;
        int ys = (tap & 2) ? y1 : y0;
        float wt = ((tap & 1) ? wx : 1.f - wx) * ((tap & 2) ? wy : 1.f - wy);
        uint4 v = xt[bbase + (size_t)(ys * 224 + xs) * 8 + c8];
        half2* hp = (half2*)&v;
        float2 f0 = __half22float2(hp[0]);
        float2 f1 = __half22float2(hp[1]);
        float2 f2 = __half22float2(hp[2]);
        float2 f3 = __half22float2(hp[3]);
        acc[0] += wt * f0.x;  acc[1] += wt * f0.y;
        acc[2] += wt * f1.x;  acc[3] += wt * f1.y;
        acc[4] += wt * f2.x;  acc[5] += wt * f2.y;
        acc[6] += wt * f3.x;  acc[7] += wt * f3.y;
    }

#pragma unroll
    for (int k = 0; k < 8; k++) {
        acc[k] += __shfl_xor_sync(0xffffffffu, acc[k], 8);
        acc[k] += __shfl_xor_sync(0xffffffffu, acc[k], 16);
    }
    if (tap == 0) {
#pragma unroll
        for (int k = 0; k < 8; k++)
            st[warpId][8 * c8 + k] = acc[k] * (1.f / 16.f);
    }
    __syncthreads();

    if (threadIdx.x < 64) {
        int c = threadIdx.x;
        int bpos = blockIdx.x * 8;
        int bB = bpos >> 9;
        int p0 = bpos & 511;
        int hB = p0 >> 5, w0 = p0 & 31;
        float4 v0 = make_float4(st[0][c], st[1][c], st[2][c], st[3][c]);
        float4 v1 = make_float4(st[4][c], st[5][c], st[6][c], st[7][c]);
        size_t ob = (((size_t)(bB * CH + c) * 64 + hB) * 128 + w0);
        *(float4*)(out + ob)     = v0;
        *(float4*)(out + ob + 4) = v1;
    }
}

// ---------------------------------------------------------------------
extern "C" void kernel_launch(void* const* d_in, const int* in_sizes, int n_in,
                              void* d_out, int out_size) {
    const float* x  = (const float*)d_in[0];
    const float* l  = (const float*)d_in[1];
    const float* w1 = (const float*)d_in[2];
    const float* b1 = (const float*)d_in[3];
    const float* w2 = (const float*)d_in[4];
    const float* b2 = (const float*)d_in[5];
    float* out  = (float*)d_out;
    float* outw = out + POOLED_ELEMS;

    k_prep<<<NTILES, 256>>>(x, l, w1, b1, w2, b2, outw);
    k_fused<<<NB_INNER + NB_FILL, 256>>>(l, out);
}

// round 7
// speedup vs baseline: 1.0157x; 1.0157x over previous
#include <cuda_runtime.h>
#include <cuda_fp16.h>
#include <math.h>

#define BATCH 8
#define CH 64
#define PLANE 50176            /* 224*224 */
#define NT 392                 /* transpose blocks per batch (128 px each) */
#define NG 64                  /* gather blocks per batch */
#define NF 128                 /* fill blocks per batch (4 iters each) */
#define SEG (NT + 1 + NG + NF) /* 585 blocks per batch */
#define POOLED_ELEMS 4194304

// ---------------- device scratch ----------------
__device__ __half g_xTh[(size_t)BATCH*PLANE*CH];  // [B][pix][C] fp16
__device__ float  g_part[BATCH*NT*CH];            // per-block channel partials
__device__ float  g_lohi[16];
__device__ float  g_cval[BATCH*CH];
__device__ float2 g_polar[8192];                  // (logr, a/pi - 1)
__device__ int    g_done[BATCH];                  // transpose completion counters
__device__ int    g_ready[BATCH];                 // per-batch MLP-done flags
__device__ int    g_fcnt[BATCH];                  // consumer counters (reset ready)

__global__ void __launch_bounds__(256) k_all(
        const float* __restrict__ x, const float* __restrict__ l,
        const float* __restrict__ w1, const float* __restrict__ b1,
        const float* __restrict__ w2, const float* __restrict__ b2,
        float* __restrict__ out, float* __restrict__ outw) {
    __shared__ float sh[64 * 33];   // 8448 B, unioned across roles
    const int bid = blockIdx.x;
    const int b   = bid / SEG;
    const int r   = bid - b * SEG;
    const int tid = threadIdx.x;

    // ============== role 1: transpose (128 px, 4 chunks of 32) ==========
    if (r < NT) {
        float (*tile)[33] = (float(*)[33])sh;
        const float4* xp = (const float4*)(x + (size_t)b * CH * PLANE);
        const int t0 = r * 128;
        float csum = 0.f;
        for (int chunk = 0; chunk < 4; chunk++) {
            if (chunk) __syncthreads();          // guard tile reuse
            const int base4 = (t0 + chunk * 32) >> 2;
#pragma unroll
            for (int it = 0; it < 2; it++) {
                int p = it * 256 + tid;
                int c = p >> 3, col4 = p & 7;
                float4 v = xp[(size_t)c * (PLANE / 4) + base4 + col4];
                tile[c][col4*4+0] = v.x; tile[c][col4*4+1] = v.y;
                tile[c][col4*4+2] = v.z; tile[c][col4*4+3] = v.w;
            }
            __syncthreads();
            if (tid < CH) {
#pragma unroll
                for (int k = 0; k < 32; k++) csum += tile[tid][k];
            }
            int rr = tid >> 3, q = tid & 7;      // 32 px x 8 quads
            half2 h0 = __floats2half2_rn(tile[8*q+0][rr], tile[8*q+1][rr]);
            half2 h1 = __floats2half2_rn(tile[8*q+2][rr], tile[8*q+3][rr]);
            half2 h2 = __floats2half2_rn(tile[8*q+4][rr], tile[8*q+5][rr]);
            half2 h3 = __floats2half2_rn(tile[8*q+6][rr], tile[8*q+7][rr]);
            uint4 u;
            u.x = *(unsigned int*)&h0; u.y = *(unsigned int*)&h1;
            u.z = *(unsigned int*)&h2; u.w = *(unsigned int*)&h3;
            ((uint4*)g_xTh)[((size_t)b * PLANE + t0 + chunk*32 + rr) * 8 + q] = u;
        }
        if (tid < CH) g_part[(b * NT + r) * CH + tid] = csum;

        // polar table: spread over first 8 blocks of batch 0
        if (b == 0 && r < 8) {
#pragma unroll
            for (int k = 0; k < 4; k++) {
                int e = r * 1024 + k * 256 + tid;
                int i = e >> 7, j = e & 127;
                float xg = (i - 32) * (1.f / 32.f);
                float yg = (j - 64) * (1.f / 64.f);
                float logr = logf(fmaxf(sqrtf(xg*xg + yg*yg), 1e-12f));
                float a = atan2f(yg, xg);
                if (!(a > 0.f)) a += 6.283185307179586f;
                g_polar[e] = make_float2(logr, a * 0.3183098861837907f - 1.f);
            }
        }
        __threadfence();
        __syncthreads();
        if (tid == 0) atomicAdd(&g_done[b], 1);
        return;
    }

    // ============== role 2: per-batch MLP block =========================
    if (r == NT) {
        if (tid == 0) {
            while (((volatile int*)g_done)[b] != NT) __nanosleep(100);
        }
        __syncthreads();
        __threadfence();
        float* br  = sh;          // [64]
        float* hid = sh + 64;     // [32]
        float* wgt = sh + 96;     // [2]
        float* red = sh + 128;    // [256]
        {
            int c = tid & 63, chunk = tid >> 6;   // 4 x 98 tiles
            float s = 0.f;
            for (int t = chunk * 98; t < chunk * 98 + 98; t++)
                s += g_part[(b * NT + t) * CH + c];
            red[tid] = s;
        }
        __syncthreads();
        if (tid < 64)
            br[tid] = (red[tid] + red[tid+64] + red[tid+128] + red[tid+192])
                      * (1.f / (float)PLANE);
        __syncthreads();
        if (tid < 32) {
            float acc = b1[tid];
#pragma unroll
            for (int c = 0; c < 64; c++) acc += br[c] * w1[c * 32 + tid];
            hid[tid] = fmaxf(acc, 0.f);
        }
        __syncthreads();
        if (tid < 2) {
            float acc = b2[tid];
#pragma unroll
            for (int m = 0; m < 32; m++) acc += hid[m] * w2[m * 2 + tid];
            float wv = 1.f / (1.f + expf(-acc));
            wgt[tid] = wv;
            outw[2 * b + tid] = wv;
        }
        __syncthreads();
        if (tid == 0) {
            g_lohi[2*b + 0] = logf(wgt[0] * 0.01f);
            g_lohi[2*b + 1] = logf(wgt[1] * 0.60f);
        }
        if (tid < 64) {   // constant-region bilinear value per channel
            float gx = l[2*b], gy = l[2*b + 1];
            float ix = fminf(fmaxf((gx + 1.f) * 112.f - 0.5f, 0.f), 223.f);
            float iy = fminf(fmaxf((gy + 1.f) * 112.f - 0.5f, 0.f), 223.f);
            float x0f = floorf(ix), y0f = floorf(iy);
            float wx = ix - x0f, wy = iy - y0f;
            int x0 = (int)x0f, y0 = (int)y0f;
            int x1 = min(x0 + 1, 223), y1 = min(y0 + 1, 223);
            const float* pp = x + (size_t)(b * CH + tid) * PLANE;
            g_cval[b * CH + tid] =
                  pp[y0*224 + x0] * (1.f-wx) * (1.f-wy)
                + pp[y0*224 + x1] * wx * (1.f-wy)
                + pp[y1*224 + x0] * (1.f-wx) * wy
                + pp[y1*224 + x1] * wx * wy;
        }
        __threadfence();
        __syncthreads();
        if (tid == 0) { g_done[b] = 0; atomicExch(&g_ready[b], 1); }
        return;
    }

    // ---- shared spin for gather/fill roles ----
    if (tid == 0) {
        while (((volatile int*)g_ready)[b] == 0) __nanosleep(100);
    }
    __syncthreads();
    __threadfence();

    // ============== role 3: gather (inner region) =======================
    if (r < NT + 1 + NG) {
        int g = r - (NT + 1);
        float (*st)[68] = (float(*)[68])sh;
        int warpId = tid >> 5, lane = tid & 31;
        int pos = g * 8 + warpId;          // 0..511 within batch
        int h = pos >> 5, w = pos & 31;
        int tap = lane >> 3, c8 = lane & 7;

        float l0 = l[2*b], l1 = l[2*b + 1];
        float lo = g_lohi[2*b], hi = g_lohi[2*b + 1];
        float inv2 = 2.f / (hi - lo);

        int s16 = lane & 15;
        int i = 4 * h + (s16 >> 2);
        int j = 4 * w + (s16 & 3);
        float2 pb = g_polar[(i << 7) | j];
        float gx = pb.y + l0;
        float gy = (pb.x - lo) * inv2 - 1.f + l1;
        float ix = fminf(fmaxf((gx + 1.f) * 112.f - 0.5f, 0.f), 223.f);
        float iy = fminf(fmaxf((gy + 1.f) * 112.f - 0.5f, 0.f), 223.f);

        const uint4* xt = (const uint4*)g_xTh;
        size_t bbase = (size_t)b * PLANE * 8;
        float acc[8];
#pragma unroll
        for (int k = 0; k < 8; k++) acc[k] = 0.f;

#pragma unroll
        for (int s = 0; s < 16; s++) {
            float ixs = __shfl_sync(0xffffffffu, ix, s);
            float iys = __shfl_sync(0xffffffffu, iy, s);
            float x0f = floorf(ixs), y0f = floorf(iys);
            float wx = ixs - x0f, wy = iys - y0f;
            int x0 = (int)x0f, y0 = (int)y0f;
            int x1 = min(x0 + 1, 223), y1 = min(y0 + 1, 223);
            int xs = (tap & 1) ? x1 : x0;
            int ys = (tap & 2) ? y1 : y0;
            float wt = ((tap & 1) ? wx : 1.f - wx) * ((tap & 2) ? wy : 1.f - wy);
            uint4 v = xt[bbase + (size_t)(ys * 224 + xs) * 8 + c8];
            half2* hp = (half2*)&v;
            float2 f0 = __half22float2(hp[0]);
            float2 f1 = __half22float2(hp[1]);
            float2 f2 = __half22float2(hp[2]);
            float2 f3 = __half22float2(hp[3]);
            acc[0] += wt * f0.x;  acc[1] += wt * f0.y;
            acc[2] += wt * f1.x;  acc[3] += wt * f1.y;
            acc[4] += wt * f2.x;  acc[5] += wt * f2.y;
            acc[6] += wt * f3.x;  acc[7] += wt * f3.y;
        }
#pragma unroll
        for (int k = 0; k < 8; k++) {
            acc[k] += __shfl_xor_sync(0xffffffffu, acc[k], 8);
            acc[k] += __shfl_xor_sync(0xffffffffu, acc[k], 16);
        }
        if (tap == 0) {
#pragma unroll
            for (int k = 0; k < 8; k++)
                st[warpId][8 * c8 + k] = acc[k] * (1.f / 16.f);
        }
        __syncthreads();
        if (tid < 64) {
            int c = tid;
            int hB = (g * 8) >> 5, w0 = (g * 8) & 31;
            float4 v0 = make_float4(st[0][c], st[1][c], st[2][c], st[3][c]);
            float4 v1 = make_float4(st[4][c], st[5][c], st[6][c], st[7][c]);
            size_t ob = (((size_t)(b * CH + c) * 64 + hB) * 128 + w0);
            *(float4*)(out + ob)     = v0;
            *(float4*)(out + ob + 4) = v1;
        }
        __syncthreads();
        if (tid == 0) {
            int o = atomicAdd(&g_fcnt[b], 1);
            if (o == NG + NF - 1) { g_fcnt[b] = 0; g_ready[b] = 0; }
        }
        return;
    }

    // ============== role 4: constant fill ===============================
    {
        int f = r - (NT + 1 + NG);        // 0..127
#pragma unroll
        for (int it = 0; it < 4; it++) {
            int idx = (f * 4 + it) * 256 + tid;   // per-batch float4 idx
            int pl  = idx >> 11;                  // local plane 0..63
            int rem = idx & 2047;
            int hh = rem >> 5, w4 = rem & 31;
            if (hh < 16 && w4 < 8) continue;      // inner handled by gather
            float v = g_cval[b * CH + pl];
            __stcs(&((float4*)out)[(size_t)(b * CH + pl) * 2048 + rem],
                   make_float4(v, v, v, v));
        }
        __syncthreads();
        if (tid == 0) {
            int o = atomicAdd(&g_fcnt[b], 1);
            if (o == NG + NF - 1) { g_fcnt[b] = 0; g_ready[b] = 0; }
        }
    }
}

// ---------------------------------------------------------------------
extern "C" void kernel_launch(void* const* d_in, const int* in_sizes, int n_in,
                              void* d_out, int out_size) {
    const float* x  = (const float*)d_in[0];
    const float* l  = (const float*)d_in[1];
    const float* w1 = (const float*)d_in[2];
    const float* b1 = (const float*)d_in[3];
    const float* w2 = (const float*)d_in[4];
    const float* b2 = (const float*)d_in[5];
    float* out  = (float*)d_out;
    float* outw = out + POOLED_ELEMS;

    k_all<<<BATCH * SEG, 256>>>(x, l, w1, b1, w2, b2, out, outw);
}

// round 8
// speedup vs baseline: 1.1447x; 1.1270x over previous
#include <cuda_runtime.h>
#include <cuda_fp16.h>
#include <math.h>

#define BATCH 8
#define CH 64
#define PLANE 50176            /* 224*224 */
#define NT 392                 /* transpose blocks per batch (128 px each) */
#define NG 64                  /* gather blocks per batch */
#define NF 128                 /* fill blocks per batch */
#define NC (1 + NG + NF)       /* consumer blocks per batch = 193 */
#define NBLK (BATCH*(NT+NC))   /* 4680 */
#define POOLED_ELEMS 4194304

// ---------------- device scratch ----------------
__device__ __half g_xTh[(size_t)BATCH*PLANE*CH];  // [B][pix][C] fp16
__device__ float  g_part[BATCH*NT*CH];            // per-block channel partials
__device__ float  g_lohi[16];
__device__ float  g_cval[BATCH*CH];
__device__ float2 g_polar[8192];                  // (logr, a/pi - 1)
__device__ int    g_done[BATCH];                  // transpose completion counters
__device__ int    g_ready[BATCH];                 // per-batch MLP-done flags
__device__ int    g_fcnt[BATCH];                  // consumer counters (reset ready)

__global__ void __launch_bounds__(256) k_all(
        const float* __restrict__ x, const float* __restrict__ l,
        const float* __restrict__ w1, const float* __restrict__ b1,
        const float* __restrict__ w2, const float* __restrict__ b2,
        float* __restrict__ out, float* __restrict__ outw) {
    __shared__ float sh[64 * 33];
    const int bid = blockIdx.x;
    const int tid = threadIdx.x;

    // ---------- bid -> (role, batch, idx): software-pipelined schedule ----
    // T0(392) T1(392) | k=0..5: [Mk Gk(64) Fk(128) T(k+2)(392)] | M6 G6 F6 M7 G7 F7
    int role, b, idx = 0;               // role: 0=T 1=M 2=G 3=F
    if (bid < 2 * NT) {
        role = 0; b = bid / NT; idx = bid - b * NT;
    } else if (bid < 2 * NT + 6 * (NC + NT)) {
        int k = (bid - 2 * NT) / (NC + NT);
        int r = (bid - 2 * NT) - k * (NC + NT);
        if (r == 0)            { role = 1; b = k; }
        else if (r < 1 + NG)   { role = 2; b = k; idx = r - 1; }
        else if (r < NC)       { role = 3; b = k; idx = r - 1 - NG; }
        else                   { role = 0; b = k + 2; idx = r - NC; }
    } else {
        int r = bid - 2 * NT - 6 * (NC + NT);   // 0..385
        int k = r / NC, r2 = r - k * NC;
        b = 6 + k;
        if (r2 == 0)           role = 1;
        else if (r2 < 1 + NG)  { role = 2; idx = r2 - 1; }
        else                   { role = 3; idx = r2 - 1 - NG; }
    }

    // ============== role 0: transpose (128 px, 4 chunks of 32) ==========
    if (role == 0) {
        float (*tile)[33] = (float(*)[33])sh;
        const float4* xp = (const float4*)(x + (size_t)b * CH * PLANE);
        const int t0 = idx * 128;
        float csum = 0.f;
        for (int chunk = 0; chunk < 4; chunk++) {
            if (chunk) __syncthreads();
            const int base4 = (t0 + chunk * 32) >> 2;
#pragma unroll
            for (int it = 0; it < 2; it++) {
                int p = it * 256 + tid;
                int c = p >> 3, col4 = p & 7;
                float4 v = xp[(size_t)c * (PLANE / 4) + base4 + col4];
                tile[c][col4*4+0] = v.x; tile[c][col4*4+1] = v.y;
                tile[c][col4*4+2] = v.z; tile[c][col4*4+3] = v.w;
            }
            __syncthreads();
            if (tid < CH) {
#pragma unroll
                for (int k = 0; k < 32; k++) csum += tile[tid][k];
            }
            int rr = tid >> 3, q = tid & 7;
            half2 h0 = __floats2half2_rn(tile[8*q+0][rr], tile[8*q+1][rr]);
            half2 h1 = __floats2half2_rn(tile[8*q+2][rr], tile[8*q+3][rr]);
            half2 h2 = __floats2half2_rn(tile[8*q+4][rr], tile[8*q+5][rr]);
            half2 h3 = __floats2half2_rn(tile[8*q+6][rr], tile[8*q+7][rr]);
            uint4 u;
            u.x = *(unsigned int*)&h0; u.y = *(unsigned int*)&h1;
            u.z = *(unsigned int*)&h2; u.w = *(unsigned int*)&h3;
            ((uint4*)g_xTh)[((size_t)b * PLANE + t0 + chunk*32 + rr) * 8 + q] = u;
        }
        if (tid < CH) g_part[(b * NT + idx) * CH + tid] = csum;

        if (b == 0 && idx < 8) {    // polar table (data-independent)
#pragma unroll
            for (int k = 0; k < 4; k++) {
                int e = idx * 1024 + k * 256 + tid;
                int i = e >> 7, j = e & 127;
                float xg = (i - 32) * (1.f / 32.f);
                float yg = (j - 64) * (1.f / 64.f);
                float logr = logf(fmaxf(sqrtf(xg*xg + yg*yg), 1e-12f));
                float a = atan2f(yg, xg);
                if (!(a > 0.f)) a += 6.283185307179586f;
                g_polar[e] = make_float2(logr, a * 0.3183098861837907f - 1.f);
            }
        }
        __threadfence();
        __syncthreads();
        if (tid == 0) atomicAdd(&g_done[b], 1);
        return;
    }

    // ============== role 1: per-batch MLP block =========================
    if (role == 1) {
        if (tid == 0) {
            while (((volatile int*)g_done)[b] != NT) __nanosleep(100);
        }
        __syncthreads();
        __threadfence();
        float* br  = sh;
        float* hid = sh + 64;
        float* wgt = sh + 96;
        float* red = sh + 128;
        {
            int c = tid & 63, chunk = tid >> 6;
            float s = 0.f;
            for (int t = chunk * 98; t < chunk * 98 + 98; t++)
                s += g_part[(b * NT + t) * CH + c];
            red[tid] = s;
        }
        __syncthreads();
        if (tid < 64)
            br[tid] = (red[tid] + red[tid+64] + red[tid+128] + red[tid+192])
                      * (1.f / (float)PLANE);
        __syncthreads();
        if (tid < 32) {
            float acc = b1[tid];
#pragma unroll
            for (int c = 0; c < 64; c++) acc += br[c] * w1[c * 32 + tid];
            hid[tid] = fmaxf(acc, 0.f);
        }
        __syncthreads();
        if (tid < 2) {
            float acc = b2[tid];
#pragma unroll
            for (int m = 0; m < 32; m++) acc += hid[m] * w2[m * 2 + tid];
            float wv = 1.f / (1.f + expf(-acc));
            wgt[tid] = wv;
            outw[2 * b + tid] = wv;
        }
        __syncthreads();
        if (tid == 0) {
            g_lohi[2*b + 0] = logf(wgt[0] * 0.01f);
            g_lohi[2*b + 1] = logf(wgt[1] * 0.60f);
        }
        if (tid < 64) {
            float gx = l[2*b], gy = l[2*b + 1];
            float ix = fminf(fmaxf((gx + 1.f) * 112.f - 0.5f, 0.f), 223.f);
            float iy = fminf(fmaxf((gy + 1.f) * 112.f - 0.5f, 0.f), 223.f);
            float x0f = floorf(ix), y0f = floorf(iy);
            float wx = ix - x0f, wy = iy - y0f;
            int x0 = (int)x0f, y0 = (int)y0f;
            int x1 = min(x0 + 1, 223), y1 = min(y0 + 1, 223);
            const float* pp = x + (size_t)(b * CH + tid) * PLANE;
            g_cval[b * CH + tid] =
                  pp[y0*224 + x0] * (1.f-wx) * (1.f-wy)
                + pp[y0*224 + x1] * wx * (1.f-wy)
                + pp[y1*224 + x0] * (1.f-wx) * wy
                + pp[y1*224 + x1] * wx * wy;
        }
        __threadfence();
        __syncthreads();
        if (tid == 0) { g_done[b] = 0; atomicExch(&g_ready[b], 1); }
        return;
    }

    // ---- shared spin for gather/fill roles (usually already set) ----
    if (tid == 0) {
        while (((volatile int*)g_ready)[b] == 0) __nanosleep(100);
    }
    __syncthreads();
    __threadfence();

    // ============== role 2: gather (inner region) =======================
    if (role == 2) {
        int g = idx;
        float (*st)[68] = (float(*)[68])sh;
        int warpId = tid >> 5, lane = tid & 31;
        int pos = g * 8 + warpId;
        int h = pos >> 5, w = pos & 31;
        int tap = lane >> 3, c8 = lane & 7;

        float l0 = l[2*b], l1 = l[2*b + 1];
        float lo = g_lohi[2*b], hi = g_lohi[2*b + 1];
        float inv2 = 2.f / (hi - lo);

        int s16 = lane & 15;
        int i = 4 * h + (s16 >> 2);
        int j = 4 * w + (s16 & 3);
        float2 pb = g_polar[(i << 7) | j];
        float gx = pb.y + l0;
        float gy = (pb.x - lo) * inv2 - 1.f + l1;
        float ix = fminf(fmaxf((gx + 1.f) * 112.f - 0.5f, 0.f), 223.f);
        float iy = fminf(fmaxf((gy + 1.f) * 112.f - 0.5f, 0.f), 223.f);

        const uint4* xt = (const uint4*)g_xTh;
        size_t bbase = (size_t)b * PLANE * 8;
        float acc[8];
#pragma unroll
        for (int k = 0; k < 8; k++) acc[k] = 0.f;

#pragma unroll
        for (int s = 0; s < 16; s++) {
            float ixs = __shfl_sync(0xffffffffu, ix, s);
            float iys = __shfl_sync(0xffffffffu, iy, s);
            float x0f = floorf(ixs), y0f = floorf(iys);
            float wx = ixs - x0f, wy = iys - y0f;
            int x0 = (int)x0f, y0 = (int)y0f;
            int x1 = min(x0 + 1, 223), y1 = min(y0 + 1, 223);
            int xs = (tap & 1) ? x1 : x0;
            int ys = (tap & 2) ? y1 : y0;
            float wt = ((tap & 1) ? wx : 1.f - wx) * ((tap & 2) ? wy : 1.f - wy);
            uint4 v = xt[bbase + (size_t)(ys * 224 + xs) * 8 + c8];
            half2* hp = (half2*)&v;
            float2 f0 = __half22float2(hp[0]);
            float2 f1 = __half22float2(hp[1]);
            float2 f2 = __half22float2(hp[2]);
            float2 f3 = __half22float2(hp[3]);
            acc[0] += wt * f0.x;  acc[1] += wt * f0.y;
            acc[2] += wt * f1.x;  acc[3] += wt * f1.y;
            acc[4] += wt * f2.x;  acc[5] += wt * f2.y;
            acc[6] += wt * f3.x;  acc[7] += wt * f3.y;
        }
#pragma unroll
        for (int k = 0; k < 8; k++) {
            acc[k] += __shfl_xor_sync(0xffffffffu, acc[k], 8);
            acc[k] += __shfl_xor_sync(0xffffffffu, acc[k], 16);
        }
        if (tap == 0) {
#pragma unroll
            for (int k = 0; k < 8; k++)
                st[warpId][8 * c8 + k] = acc[k] * (1.f / 16.f);
        }
        __syncthreads();
        if (tid < 64) {
            int c = tid;
            int hB = (g * 8) >> 5, w0 = (g * 8) & 31;
            float4 v0 = make_float4(st[0][c], st[1][c], st[2][c], st[3][c]);
            float4 v1 = make_float4(st[4][c], st[5][c], st[6][c], st[7][c]);
            size_t ob = (((size_t)(b * CH + c) * 64 + hB) * 128 + w0);
            *(float4*)(out + ob)     = v0;
            *(float4*)(out + ob + 4) = v1;
        }
        __syncthreads();
        if (tid == 0) {
            int o = atomicAdd(&g_fcnt[b], 1);
            if (o == NG + NF - 1) { g_fcnt[b] = 0; g_ready[b] = 0; }
        }
        return;
    }

    // ============== role 3: constant fill ===============================
    {
        int f = idx;
#pragma unroll
        for (int it = 0; it < 4; it++) {
            int e = (f * 4 + it) * 256 + tid;
            int pl  = e >> 11;
            int rem = e & 2047;
            int hh = rem >> 5, w4 = rem & 31;
            if (hh < 16 && w4 < 8) continue;
            float v = g_cval[b * CH + pl];
            __stcs(&((float4*)out)[(size_t)(b * CH + pl) * 2048 + rem],
                   make_float4(v, v, v, v));
        }
        __syncthreads();
        if (tid == 0) {
            int o = atomicAdd(&g_fcnt[b], 1);
            if (o == NG + NF - 1) { g_fcnt[b] = 0; g_ready[b] = 0; }
        }
    }
}

// ---------------------------------------------------------------------
extern "C" void kernel_launch(void* const* d_in, const int* in_sizes, int n_in,
                              void* d_out, int out_size) {
    const float* x  = (const float*)d_in[0];
    const float* l  = (const float*)d_in[1];
    const float* w1 = (const float*)d_in[2];
    const float* b1 = (const float*)d_in[3];
    const float* w2 = (const float*)d_in[4];
    const float* b2 = (const float*)d_in[5];
    float* out  = (float*)d_out;
    float* outw = out + POOLED_ELEMS;

    k_all<<<NBLK, 256>>>(x, l, w1, b1, w2, b2, out, outw);
}